// round 1
// baseline (speedup 1.0000x reference)
#include <cuda_runtime.h>

#define DEV_INLINE __device__ __forceinline__

// Problem constants
constexpr int BATCH = 32;
constexpr int SEQ   = 1024;
constexpr int HD    = 256;
constexpr int MTOT  = BATCH * SEQ;   // 32768

// GEMM tiling
constexpr int BM = 128, BN = 128, BK = 16;
constexpr int NTST = 20;    // padded smem stride for NT tiles ([row][k])
constexpr int NNST = 132;   // padded smem stride for NN B tiles ([k][n])
constexpr int TILE_WORDS = BM * NTST;  // 2560 floats

// ---------------------------------------------------------------------------
// Scratch (device globals: the sanctioned no-alloc path)
// ---------------------------------------------------------------------------
__device__ float g_Q [(size_t)MTOT * HD];
__device__ float g_K [(size_t)MTOT * HD];
__device__ float g_V [(size_t)MTOT * HD];
__device__ float g_O [(size_t)MTOT * HD];
__device__ float g_X1[(size_t)MTOT * HD];
__device__ float g_T1[(size_t)MTOT * HD];
__device__ float g_T2[(size_t)MTOT * HD];
__device__ float g_F [(size_t)MTOT * HD];
__device__ float g_S [(size_t)BATCH * SEQ * SEQ];   // 128 MB scores/probs

// ---------------------------------------------------------------------------
// Helpers
// ---------------------------------------------------------------------------
DEV_INLINE float to_tf32(float x) {
    unsigned u;
    asm("cvt.rna.tf32.f32 %0, %1;" : "=r"(u) : "f"(x));
    return __uint_as_float(u);
}

DEV_INLINE unsigned f2b(float x) { return __float_as_uint(x); }

DEV_INLINE void mma_tf32(float c[4], const unsigned a[4], const unsigned b[2]) {
    asm volatile(
        "mma.sync.aligned.m16n8k8.row.col.f32.tf32.tf32.f32 "
        "{%0,%1,%2,%3}, {%4,%5,%6,%7}, {%8,%9}, {%0,%1,%2,%3};"
        : "+f"(c[0]), "+f"(c[1]), "+f"(c[2]), "+f"(c[3])
        : "r"(a[0]), "r"(a[1]), "r"(a[2]), "r"(a[3]), "r"(b[0]), "r"(b[1]));
}

DEV_INLINE float wsum(float v) {
    #pragma unroll
    for (int o = 16; o; o >>= 1) v += __shfl_xor_sync(0xffffffffu, v, o);
    return v;
}

// ---------------------------------------------------------------------------
// Generic tf32 GEMM: C[M,N] = A[M,K] @ B' (+ epilogue)
//   BNT=true : B is [N,K] row-major (NT — weights, QK^T)
//   BNT=false: B is [K,N] row-major (NN — P@V)
//   EPI: 0 = +bias[col]; 1 = scores (scale + mask bias); 2 = plain store
// All dims multiples of tile sizes. 256 threads, 8 warps (4m x 2n), warp 32x64.
// ---------------------------------------------------------------------------
template<int EPI, bool BNT>
__global__ void __launch_bounds__(256) gemm_k(
    const float* __restrict__ Ag, const float* __restrict__ Bg,
    const float* __restrict__ aux, float* __restrict__ Cg,
    int Kdim, int ldA, int ldB, int ldC,
    size_t sA, size_t sB, size_t sC, int auxStride)
{
    __shared__ float sA2[2][TILE_WORDS];
    __shared__ float sB2[2][TILE_WORDS];

    const int z = blockIdx.z;
    const float* A    = Ag  + (size_t)z * sA;
    const float* B    = Bg  + (size_t)z * sB;
    float*       C    = Cg  + (size_t)z * sC;
    const float* auxp = aux + (size_t)z * auxStride;

    const int m0 = blockIdx.y * BM;
    const int n0 = blockIdx.x * BN;
    const int tid  = threadIdx.x;
    const int warp = tid >> 5, lane = tid & 31;
    const int wm = warp >> 1, wn = warp & 1;
    const int gr = lane >> 2, tig = lane & 3;

    float acc[2][8][4];
    #pragma unroll
    for (int t = 0; t < 2; t++)
        #pragma unroll
        for (int j = 0; j < 8; j++)
            #pragma unroll
            for (int q = 0; q < 4; q++) acc[t][j][q] = 0.f;

    const int ar  = tid >> 2;           // 0..63 (row pair for NT tiles)
    const int ac  = (tid & 3) * 4;      // 0,4,8,12
    const int bkr = tid >> 5;           // 0..7  (k row for NN tiles)
    const int bnc = (tid & 31) * 4;     // 0..124

    float4 ra[2], rb[2];

    auto stage = [&](int buf) {
        float* pa0 = &sA2[buf][ar * NTST + ac];
        pa0[0]=to_tf32(ra[0].x); pa0[1]=to_tf32(ra[0].y); pa0[2]=to_tf32(ra[0].z); pa0[3]=to_tf32(ra[0].w);
        float* pa1 = &sA2[buf][(ar + 64) * NTST + ac];
        pa1[0]=to_tf32(ra[1].x); pa1[1]=to_tf32(ra[1].y); pa1[2]=to_tf32(ra[1].z); pa1[3]=to_tf32(ra[1].w);
        if (BNT) {
            float* pb0 = &sB2[buf][ar * NTST + ac];
            pb0[0]=to_tf32(rb[0].x); pb0[1]=to_tf32(rb[0].y); pb0[2]=to_tf32(rb[0].z); pb0[3]=to_tf32(rb[0].w);
            float* pb1 = &sB2[buf][(ar + 64) * NTST + ac];
            pb1[0]=to_tf32(rb[1].x); pb1[1]=to_tf32(rb[1].y); pb1[2]=to_tf32(rb[1].z); pb1[3]=to_tf32(rb[1].w);
        } else {
            float* pb0 = &sB2[buf][bkr * NNST + bnc];
            pb0[0]=to_tf32(rb[0].x); pb0[1]=to_tf32(rb[0].y); pb0[2]=to_tf32(rb[0].z); pb0[3]=to_tf32(rb[0].w);
            float* pb1 = &sB2[buf][(bkr + 8) * NNST + bnc];
            pb1[0]=to_tf32(rb[1].x); pb1[1]=to_tf32(rb[1].y); pb1[2]=to_tf32(rb[1].z); pb1[3]=to_tf32(rb[1].w);
        }
    };

    auto gload = [&](int k0) {
        const float* ap = A + (size_t)(m0 + ar) * ldA + k0 + ac;
        ra[0] = *(const float4*)ap;
        ra[1] = *(const float4*)(ap + (size_t)64 * ldA);
        if (BNT) {
            const float* bp = B + (size_t)(n0 + ar) * ldB + k0 + ac;
            rb[0] = *(const float4*)bp;
            rb[1] = *(const float4*)(bp + (size_t)64 * ldB);
        } else {
            const float* bp = B + (size_t)(k0 + bkr) * ldB + n0 + bnc;
            rb[0] = *(const float4*)bp;
            rb[1] = *(const float4*)(bp + (size_t)8 * ldB);
        }
    };

    gload(0);
    stage(0);
    __syncthreads();

    const int KB = Kdim / BK;
    for (int kt = 0; kt < KB; kt++) {
        const int cur = kt & 1;
        const bool more = (kt + 1 < KB);
        if (more) gload((kt + 1) * BK);

        #pragma unroll
        for (int kk = 0; kk < 2; kk++) {
            unsigned af[2][4];
            #pragma unroll
            for (int t = 0; t < 2; t++) {
                const int r = wm * 32 + t * 16 + gr;
                const float* pa = &sA2[cur][r * NTST + kk * 8 + tig];
                af[t][0] = f2b(pa[0]);
                af[t][1] = f2b(pa[8 * NTST]);
                af[t][2] = f2b(pa[4]);
                af[t][3] = f2b(pa[8 * NTST + 4]);
            }
            #pragma unroll
            for (int j = 0; j < 8; j++) {
                unsigned bf[2];
                if (BNT) {
                    const float* pb = &sB2[cur][(wn * 64 + j * 8 + gr) * NTST + kk * 8 + tig];
                    bf[0] = f2b(pb[0]);
                    bf[1] = f2b(pb[4]);
                } else {
                    const float* pb = &sB2[cur][(kk * 8 + tig) * NNST + wn * 64 + j * 8 + gr];
                    bf[0] = f2b(pb[0]);
                    bf[1] = f2b(pb[4 * NNST]);
                }
                #pragma unroll
                for (int t = 0; t < 2; t++) mma_tf32(acc[t][j], af[t], bf);
            }
        }

        if (more) stage(cur ^ 1);
        __syncthreads();
    }

    // Epilogue
    const float SCALE = 0.0625f;  // 1/sqrt(256)
    #pragma unroll
    for (int t = 0; t < 2; t++) {
        const int r0 = m0 + wm * 32 + t * 16 + gr;
        const int r1 = r0 + 8;
        #pragma unroll
        for (int j = 0; j < 8; j++) {
            const int c = n0 + wn * 64 + j * 8 + 2 * tig;
            float x0 = acc[t][j][0], x1 = acc[t][j][1];
            float x2 = acc[t][j][2], x3 = acc[t][j][3];
            if (EPI == 0) {
                const float b0 = auxp[c], b1 = auxp[c + 1];
                float2 v0 = {x0 + b0, x1 + b1};
                float2 v1 = {x2 + b0, x3 + b1};
                *(float2*)&C[(size_t)r0 * ldC + c] = v0;
                *(float2*)&C[(size_t)r1 * ldC + c] = v1;
            } else if (EPI == 1) {
                // rows r0/r1 are within-batch query indices here (M = 1024)
                const float mq0 = auxp[r0 - m0 + m0];  // auxp indexed by in-batch row
                const float mq1 = auxp[r1];
                const float mqA = auxp[r0];
                const float mc0 = auxp[c], mc1 = auxp[c + 1];
                (void)mq0;
                float2 v0, v1;
                v0.x = x0 * SCALE + ((mqA * mc0 > 0.5f) ? 1.f : -1e5f);
                v0.y = x1 * SCALE + ((mqA * mc1 > 0.5f) ? 1.f : -1e5f);
                v1.x = x2 * SCALE + ((mq1 * mc0 > 0.5f) ? 1.f : -1e5f);
                v1.y = x3 * SCALE + ((mq1 * mc1 > 0.5f) ? 1.f : -1e5f);
                *(float2*)&C[(size_t)r0 * ldC + c] = v0;
                *(float2*)&C[(size_t)r1 * ldC + c] = v1;
            } else {
                float2 v0 = {x0, x1};
                float2 v1 = {x2, x3};
                *(float2*)&C[(size_t)r0 * ldC + c] = v0;
                *(float2*)&C[(size_t)r1 * ldC + c] = v1;
            }
        }
    }
}

// ---------------------------------------------------------------------------
// Row softmax over length-1024 rows of S (in place). One 256-thread block/row.
// ---------------------------------------------------------------------------
__global__ void __launch_bounds__(256) softmax_k(float* __restrict__ S)
{
    __shared__ float red[8];
    float* p = S + (size_t)blockIdx.x * SEQ;
    const int tid = threadIdx.x;

    float4 v = reinterpret_cast<float4*>(p)[tid];
    float m = fmaxf(fmaxf(v.x, v.y), fmaxf(v.z, v.w));
    #pragma unroll
    for (int o = 16; o; o >>= 1) m = fmaxf(m, __shfl_xor_sync(0xffffffffu, m, o));
    if ((tid & 31) == 0) red[tid >> 5] = m;
    __syncthreads();
    m = red[0];
    #pragma unroll
    for (int i = 1; i < 8; i++) m = fmaxf(m, red[i]);
    __syncthreads();

    v.x = expf(v.x - m); v.y = expf(v.y - m);
    v.z = expf(v.z - m); v.w = expf(v.w - m);
    float s = v.x + v.y + v.z + v.w;
    #pragma unroll
    for (int o = 16; o; o >>= 1) s += __shfl_xor_sync(0xffffffffu, s, o);
    if ((tid & 31) == 0) red[tid >> 5] = s;
    __syncthreads();
    s = red[0];
    #pragma unroll
    for (int i = 1; i < 8; i++) s += red[i];

    const float inv = 1.f / s;
    v.x *= inv; v.y *= inv; v.z *= inv; v.w *= inv;
    reinterpret_cast<float4*>(p)[tid] = v;
}

// ---------------------------------------------------------------------------
// Y = relu(LN(X)) rowwise over H=256. One warp per row, 8 rows per block.
// ---------------------------------------------------------------------------
__global__ void __launch_bounds__(256) relu_ln_k(
    const float* __restrict__ X, const float* __restrict__ G,
    const float* __restrict__ Bt, float* __restrict__ Y)
{
    const int row  = blockIdx.x * 8 + (threadIdx.x >> 5);
    const int lane = threadIdx.x & 31;
    const float4* x4 = reinterpret_cast<const float4*>(X + (size_t)row * HD);
    float4 a = x4[lane], b = x4[lane + 32];

    float s = a.x + a.y + a.z + a.w + b.x + b.y + b.z + b.w;
    s = wsum(s);
    const float mu = s * (1.f / HD);
    a.x -= mu; a.y -= mu; a.z -= mu; a.w -= mu;
    b.x -= mu; b.y -= mu; b.z -= mu; b.w -= mu;
    float q = a.x*a.x + a.y*a.y + a.z*a.z + a.w*a.w
            + b.x*b.x + b.y*b.y + b.z*b.z + b.w*b.w;
    q = wsum(q);
    const float inv = rsqrtf(q * (1.f / HD) + 1e-5f);

    const float4* g4 = reinterpret_cast<const float4*>(G);
    const float4* c4 = reinterpret_cast<const float4*>(Bt);
    float4 g0 = g4[lane], g1 = g4[lane + 32];
    float4 c0 = c4[lane], c1 = c4[lane + 32];

    float4 o0, o1;
    o0.x = fmaxf(a.x * inv * g0.x + c0.x, 0.f);
    o0.y = fmaxf(a.y * inv * g0.y + c0.y, 0.f);
    o0.z = fmaxf(a.z * inv * g0.z + c0.z, 0.f);
    o0.w = fmaxf(a.w * inv * g0.w + c0.w, 0.f);
    o1.x = fmaxf(b.x * inv * g1.x + c1.x, 0.f);
    o1.y = fmaxf(b.y * inv * g1.y + c1.y, 0.f);
    o1.z = fmaxf(b.z * inv * g1.z + c1.z, 0.f);
    o1.w = fmaxf(b.w * inv * g1.w + c1.w, 0.f);

    float4* y4 = reinterpret_cast<float4*>(Y + (size_t)row * HD);
    y4[lane] = o0; y4[lane + 32] = o1;
}

// ---------------------------------------------------------------------------
// Y = LN(Xa;Ga,Ba) + LN(Xb;Gb,Bb), optional relu. One warp per row.
// ---------------------------------------------------------------------------
__global__ void __launch_bounds__(256) dual_ln_add_k(
    const float* __restrict__ Xa, const float* __restrict__ Xb,
    const float* __restrict__ Ga, const float* __restrict__ Ba,
    const float* __restrict__ Gb, const float* __restrict__ Bb,
    float* __restrict__ Y, int doRelu)
{
    const int row  = blockIdx.x * 8 + (threadIdx.x >> 5);
    const int lane = threadIdx.x & 31;

    const float4* xa4 = reinterpret_cast<const float4*>(Xa + (size_t)row * HD);
    const float4* xb4 = reinterpret_cast<const float4*>(Xb + (size_t)row * HD);
    float4 a0 = xa4[lane], a1 = xa4[lane + 32];
    float4 b0 = xb4[lane], b1 = xb4[lane + 32];

    float sa = a0.x+a0.y+a0.z+a0.w + a1.x+a1.y+a1.z+a1.w;
    float sb = b0.x+b0.y+b0.z+b0.w + b1.x+b1.y+b1.z+b1.w;
    sa = wsum(sa); sb = wsum(sb);
    const float mua = sa * (1.f / HD), mub = sb * (1.f / HD);
    a0.x-=mua; a0.y-=mua; a0.z-=mua; a0.w-=mua;
    a1.x-=mua; a1.y-=mua; a1.z-=mua; a1.w-=mua;
    b0.x-=mub; b0.y-=mub; b0.z-=mub; b0.w-=mub;
    b1.x-=mub; b1.y-=mub; b1.z-=mub; b1.w-=mub;
    float qa = a0.x*a0.x+a0.y*a0.y+a0.z*a0.z+a0.w*a0.w
             + a1.x*a1.x+a1.y*a1.y+a1.z*a1.z+a1.w*a1.w;
    float qb = b0.x*b0.x+b0.y*b0.y+b0.z*b0.z+b0.w*b0.w
             + b1.x*b1.x+b1.y*b1.y+b1.z*b1.z+b1.w*b1.w;
    qa = wsum(qa); qb = wsum(qb);
    const float inva = rsqrtf(qa * (1.f / HD) + 1e-5f);
    const float invb = rsqrtf(qb * (1.f / HD) + 1e-5f);

    const float4* ga4 = reinterpret_cast<const float4*>(Ga);
    const float4* ba4 = reinterpret_cast<const float4*>(Ba);
    const float4* gb4 = reinterpret_cast<const float4*>(Gb);
    const float4* bb4 = reinterpret_cast<const float4*>(Bb);
    float4 ga0 = ga4[lane], ga1 = ga4[lane + 32];
    float4 ca0 = ba4[lane], ca1 = ba4[lane + 32];
    float4 gb0 = gb4[lane], gb1 = gb4[lane + 32];
    float4 cb0 = bb4[lane], cb1 = bb4[lane + 32];

    float4 o0, o1;
    o0.x = (a0.x*inva*ga0.x + ca0.x) + (b0.x*invb*gb0.x + cb0.x);
    o0.y = (a0.y*inva*ga0.y + ca0.y) + (b0.y*invb*gb0.y + cb0.y);
    o0.z = (a0.z*inva*ga0.z + ca0.z) + (b0.z*invb*gb0.z + cb0.z);
    o0.w = (a0.w*inva*ga0.w + ca0.w) + (b0.w*invb*gb0.w + cb0.w);
    o1.x = (a1.x*inva*ga1.x + ca1.x) + (b1.x*invb*gb1.x + cb1.x);
    o1.y = (a1.y*inva*ga1.y + ca1.y) + (b1.y*invb*gb1.y + cb1.y);
    o1.z = (a1.z*inva*ga1.z + ca1.z) + (b1.z*invb*gb1.z + cb1.z);
    o1.w = (a1.w*inva*ga1.w + ca1.w) + (b1.w*invb*gb1.w + cb1.w);
    if (doRelu) {
        o0.x = fmaxf(o0.x, 0.f); o0.y = fmaxf(o0.y, 0.f);
        o0.z = fmaxf(o0.z, 0.f); o0.w = fmaxf(o0.w, 0.f);
        o1.x = fmaxf(o1.x, 0.f); o1.y = fmaxf(o1.y, 0.f);
        o1.z = fmaxf(o1.z, 0.f); o1.w = fmaxf(o1.w, 0.f);
    }

    float4* y4 = reinterpret_cast<float4*>(Y + (size_t)row * HD);
    y4[lane] = o0; y4[lane + 32] = o1;
}

// ---------------------------------------------------------------------------
// Host launch
// ---------------------------------------------------------------------------
extern "C" void kernel_launch(void* const* d_in, const int* in_sizes, int n_in,
                              void* d_out, int out_size)
{
    (void)in_sizes; (void)n_in; (void)out_size;
    const float* feats   = (const float*)d_in[0];
    const float* masks   = (const float*)d_in[1];
    const float* qw      = (const float*)d_in[2];
    const float* qbias   = (const float*)d_in[3];
    const float* kw      = (const float*)d_in[4];
    const float* kbias   = (const float*)d_in[5];
    const float* vw      = (const float*)d_in[6];
    const float* vbias   = (const float*)d_in[7];
    const float* alng    = (const float*)d_in[8];
    const float* alnb    = (const float*)d_in[9];
    const float* caw     = (const float*)d_in[10];
    const float* cabias  = (const float*)d_in[11];
    const float* calng   = (const float*)d_in[12];
    const float* calnb   = (const float*)d_in[13];
    const float* lw      = (const float*)d_in[14];
    const float* lbias   = (const float*)d_in[15];
    const float* llng    = (const float*)d_in[16];
    const float* llnb    = (const float*)d_in[17];
    float* out = (float*)d_out;

    float *Q, *K, *V, *O, *X1, *T1, *T2, *F, *S;
    cudaGetSymbolAddress((void**)&Q,  g_Q);
    cudaGetSymbolAddress((void**)&K,  g_K);
    cudaGetSymbolAddress((void**)&V,  g_V);
    cudaGetSymbolAddress((void**)&O,  g_O);
    cudaGetSymbolAddress((void**)&X1, g_X1);
    cudaGetSymbolAddress((void**)&T1, g_T1);
    cudaGetSymbolAddress((void**)&T2, g_T2);
    cudaGetSymbolAddress((void**)&F,  g_F);
    cudaGetSymbolAddress((void**)&S,  g_S);

    const dim3 blk(256);
    const dim3 gProj(HD / BN, MTOT / BM, 1);          // (2, 256)
    const dim3 gScore(SEQ / BN, SEQ / BM, BATCH);     // (8, 8, 32)
    const dim3 gPV(HD / BN, SEQ / BM, BATCH);         // (2, 8, 32)

    for (int i = 0; i < 3; i++) {
        const float* Fin = (i == 0) ? feats : F;
        const size_t wOff = (size_t)i * HD * HD;
        const size_t bOff = (size_t)i * HD;

        gemm_k<0, true><<<gProj, blk>>>(Fin, qw + wOff, qbias + bOff, Q,
                                        HD, HD, HD, HD, 0, 0, 0, 0);
        gemm_k<0, true><<<gProj, blk>>>(Fin, kw + wOff, kbias + bOff, K,
                                        HD, HD, HD, HD, 0, 0, 0, 0);
        gemm_k<0, true><<<gProj, blk>>>(Fin, vw + wOff, vbias + bOff, V,
                                        HD, HD, HD, HD, 0, 0, 0, 0);

        gemm_k<1, true><<<gScore, blk>>>(Q, K, masks, S,
                                         HD, HD, HD, SEQ,
                                         (size_t)SEQ * HD, (size_t)SEQ * HD,
                                         (size_t)SEQ * SEQ, SEQ);

        softmax_k<<<MTOT, blk>>>(S);

        gemm_k<2, false><<<gPV, blk>>>(S, V, V /*unused*/, O,
                                       SEQ, SEQ, HD, HD,
                                       (size_t)SEQ * SEQ, (size_t)SEQ * HD,
                                       (size_t)SEQ * HD, 0);

        relu_ln_k<<<MTOT / 8, blk>>>(O, alng + bOff, alnb + bOff, X1);

        gemm_k<0, true><<<gProj, blk>>>(X1, caw + wOff, cabias + bOff, T1,
                                        HD, HD, HD, HD, 0, 0, 0, 0);
        gemm_k<0, true><<<gProj, blk>>>(Fin, lw + wOff, lbias + bOff, T2,
                                        HD, HD, HD, HD, 0, 0, 0, 0);

        dual_ln_add_k<<<MTOT / 8, blk>>>(T1, T2,
                                         calng + bOff, calnb + bOff,
                                         llng + bOff, llnb + bOff,
                                         (i == 2) ? out : F, (i < 2) ? 1 : 0);
    }
}